// round 3
// baseline (speedup 1.0000x reference)
#include <cuda_runtime.h>

// CAM_43344809951340: per-sample symmetric tanh outer-product attention.
// T[i][j] = tanh(av_i*av_j*s), symmetric 64x64; rows contracted with Wca/Wcv.
// Warp handles S=5 register-batched samples; lane l owns rows l and l+32.
// XOR pairing computes each unique tanh once (2 tanh / 4 shfl per (m,k) unit
// = provable MIO/MUFU-balanced minimum). This round: occupancy up (S=5,
// regs<=46 -> 44 warps/SM), LDS.128 fused weight table, prefetched
// work-stealing batch id.

#define RS 0.35355339059327379f   // sqrt(1/8)
#define S 5

__device__ int g_cam_counter;

__device__ __forceinline__ float tanhf_a(float x) {
    float y;
    asm("tanh.approx.f32 %0, %1;" : "=f"(y) : "f"(x));
    return y;
}

__global__ __launch_bounds__(128, 11)
void cam_kernel(const float* __restrict__ f1, const float* __restrict__ f2,
                const float* __restrict__ Wca, const float* __restrict__ Wcv,
                float* __restrict__ out, int B)
{
    // Fused per-(m,lane) weight table (one LDS.128 per m):
    //  .x = Wca[l^m]        (lo-lo pair weight, row l)
    //  .y = Wcv[(l^m)+32]   (hi-hi pair weight, row l+32)
    //  .z = Wca[(l^m)+32]   (cross weight, row l)
    //  .w = Wcv[l^m]        (cross weight, row l+32)
    __shared__ float4 wq[31][32];

    const int tid = threadIdx.x;
    for (int idx = tid; idx < 31 * 32; idx += blockDim.x) {
        int m = (idx >> 5) + 1;
        int l2 = idx & 31;
        int j = l2 ^ m;
        wq[m - 1][l2] = make_float4(Wca[j], Wcv[j + 32], Wca[j + 32], Wcv[j]);
    }
    __syncthreads();

    const int l = tid & 31;
    const float wd0 = Wca[l];       // diag row l
    const float wd1 = Wcv[l + 32];  // diag row l+32
    const float wm0 = Wca[l + 32];  // pair (l, l+32)
    const float wm1 = Wcv[l];       // pair (l+32, l)

    const int nbatch = (B + S - 1) / S;

    // Work stealing with one-deep prefetch to hide ATOMG latency.
    int batch = 0;
    if (l == 0) batch = atomicAdd(&g_cam_counter, 1);
    batch = __shfl_sync(0xffffffffu, batch, 0);

    while (batch < nbatch) {
        int nextb = 0;
        if (l == 0) nextb = atomicAdd(&g_cam_counter, 1);  // overlaps compute
        nextb = __shfl_sync(0xffffffffu, nextb, 0);

        const int base = batch * S;
        const bool full = (base + S <= B);

        float al[S], ah[S], a0[S], a1[S];
        #pragma unroll
        for (int k = 0; k < S; k++) {
            int b = base + k;
            bool v = full || (b < B);
            float x0 = v ? f1[b * 32 + l] : 0.0f;
            float x1 = v ? f2[b * 32 + l] : 0.0f;
            a0[k] = x0; a1[k] = x1;            // residuals / accumulators
            al[k] = x0 * RS; ah[k] = x1 * RS;  // pre-scaled av halves
        }

        // Diagonal + (l, l+32) pair — no communication needed
        #pragma unroll
        for (int k = 0; k < S; k++) {
            a0[k] = fmaf(tanhf_a(al[k] * al[k]), wd0, a0[k]);
            a1[k] = fmaf(tanhf_a(ah[k] * ah[k]), wd1, a1[k]);
            float t = tanhf_a(al[k] * ah[k]);
            a0[k] = fmaf(t, wm0, a0[k]);
            a1[k] = fmaf(t, wm1, a1[k]);
        }

        // Rolled m-loop keeps body in L0 I$.
        #pragma unroll 1
        for (int m = 1; m < 32; m++) {
            const bool lo = l < (l ^ m);
            const float4 w = wq[m - 1][l];
            #pragma unroll
            for (int k = 0; k < S; k++) {
                // lo-lo / hi-hi: one tanh per lane-pair, exchanged once.
                float send = lo ? ah[k] : al[k];
                float x    = __shfl_xor_sync(0xffffffffu, send, m);
                float sc   = lo ? al[k] : ah[k];
                float t    = tanhf_a(sc * x);
                float to   = __shfl_xor_sync(0xffffffffu, t, m);
                float tl_  = lo ? t : to;   // T[l][l^m]
                float th_  = lo ? to : t;   // T[l+32][(l^m)+32]
                a0[k] = fmaf(tl_, w.x, a0[k]);
                a1[k] = fmaf(th_, w.y, a1[k]);
                // cross-half: T[l][(l^m)+32]; partner's value is T[l+32][l^m].
                float xh = __shfl_xor_sync(0xffffffffu, ah[k], m);
                float ta = tanhf_a(al[k] * xh);
                float tb = __shfl_xor_sync(0xffffffffu, ta, m);
                a0[k] = fmaf(ta, w.z, a0[k]);
                a1[k] = fmaf(tb, w.w, a1[k]);
            }
        }

        #pragma unroll
        for (int k = 0; k < S; k++) {
            int b = base + k;
            if (full || (b < B)) {
                out[b * 64 + l]      = 0.1f * fmaxf(a0[k], 0.0f);
                out[b * 64 + 32 + l] = 0.1f * fmaxf(a1[k], 0.0f);
            }
        }

        batch = nextb;
    }
}

extern "C" void kernel_launch(void* const* d_in, const int* in_sizes, int n_in,
                              void* d_out, int out_size) {
    const float* f1  = (const float*)d_in[0];
    const float* f2  = (const float*)d_in[1];
    const float* Wca = (const float*)d_in[2];
    const float* Wcv = (const float*)d_in[3];
    float* out = (float*)d_out;

    const int B = in_sizes[0] / 32;

    void* ctr = nullptr;
    cudaGetSymbolAddress(&ctr, g_cam_counter);
    cudaMemsetAsync(ctr, 0, sizeof(int));

    // 11 blocks/SM x 148 SMs; work stealing balances the tail.
    cam_kernel<<<1628, 128>>>(f1, f2, Wca, Wcv, out, B);
}

// round 4
// speedup vs baseline: 1.1165x; 1.1165x over previous
#include <cuda_runtime.h>

// CAM_43344809951340: per-sample symmetric tanh outer-product attention.
// T[i][j] = tanh(av_i*av_j*s), symmetric 64x64; rows contracted with Wca/Wcv.
// Lane l owns rows l and l+32. XOR pairing computes each unique tanh once.
// NEW: samples processed in f16x2 PAIRS — one tanh.approx.f16x2 = 2 tanhs,
// one SHFL = 2 values. Accumulation in f32 via packed fma.rn.f32x2.
// MUFU and MIO floors halve; issue becomes the single binding pipe.

#define RS 0.35355339059327379f   // sqrt(1/8)
#define S 8                       // samples per warp-iteration (4 f16x2 pairs)
#define P 4

typedef unsigned long long u64;
typedef unsigned int u32;

__device__ int g_cam_counter;

// ---- packed-op helpers ----
__device__ __forceinline__ u64 ffma2(u64 a, u64 b, u64 c) {
    u64 d; asm("fma.rn.f32x2 %0,%1,%2,%3;" : "=l"(d) : "l"(a), "l"(b), "l"(c));
    return d;
}
__device__ __forceinline__ u64 pack2(float lo, float hi) {
    u64 d; asm("mov.b64 %0,{%1,%2};" : "=l"(d) : "f"(lo), "f"(hi));
    return d;
}
__device__ __forceinline__ float2 unpack2(u64 a) {
    float2 r; asm("mov.b64 {%0,%1},%2;" : "=f"(r.x), "=f"(r.y) : "l"(a));
    return r;
}
__device__ __forceinline__ u32 hmul2(u32 a, u32 b) {
    u32 d; asm("mul.rn.f16x2 %0,%1,%2;" : "=r"(d) : "r"(a), "r"(b));
    return d;
}
__device__ __forceinline__ u32 tanh2(u32 a) {
    u32 d; asm("tanh.approx.f16x2 %0,%1;" : "=r"(d) : "r"(a));
    return d;
}
// pack two f32 into f16x2: first asm source -> high half, second -> low half
__device__ __forceinline__ u32 f2h2(float lo, float hi) {
    u32 d; asm("cvt.rn.f16x2.f32 %0,%1,%2;" : "=r"(d) : "f"(hi), "f"(lo));
    return d;
}
// widen f16x2 -> f32x2 (order preserved: low->low)
__device__ __forceinline__ u64 h2f2(u32 h) {
    u64 d;
    asm("{.reg .f16 h0,h1; .reg .f32 f0,f1;\n\t"
        "mov.b32 {h0,h1},%1;\n\t"
        "cvt.f32.f16 f0,h0; cvt.f32.f16 f1,h1;\n\t"
        "mov.b64 %0,{f0,f1};}" : "=l"(d) : "r"(h));
    return d;
}

__global__ __launch_bounds__(128, 8)
void cam_kernel(const float* __restrict__ f1, const float* __restrict__ f2,
                const float* __restrict__ Wca, const float* __restrict__ Wcv,
                float* __restrict__ out, int B)
{
    // Fused per-(m,lane) weight table (one LDS.128 per m):
    //  .x = Wca[l^m]      (lo-lo pair, row l)    .y = Wcv[(l^m)+32] (hi-hi, row l+32)
    //  .z = Wca[(l^m)+32] (cross, row l)         .w = Wcv[l^m]      (cross, row l+32)
    __shared__ float4 wq[31][32];

    const int tid = threadIdx.x;
    for (int idx = tid; idx < 31 * 32; idx += blockDim.x) {
        int m = (idx >> 5) + 1;
        int l2 = idx & 31;
        int j = l2 ^ m;
        wq[m - 1][l2] = make_float4(Wca[j], Wcv[j + 32], Wca[j + 32], Wcv[j]);
    }
    __syncthreads();

    const int l = tid & 31;
    // broadcast-packed per-lane constant weights
    const u64 wdd0 = pack2(Wca[l], Wca[l]);            // diag row l
    const u64 wdd1 = pack2(Wcv[l + 32], Wcv[l + 32]);  // diag row l+32
    const u64 wmm0 = pack2(Wca[l + 32], Wca[l + 32]);  // pair (l,l+32) -> row l
    const u64 wmm1 = pack2(Wcv[l], Wcv[l]);            // pair (l+32,l) -> row l+32

    const int nbatch = (B + S - 1) / S;

    int batch = 0;
    if (l == 0) batch = atomicAdd(&g_cam_counter, 1);
    batch = __shfl_sync(0xffffffffu, batch, 0);

    while (batch < nbatch) {
        int nextb = 0;
        if (l == 0) nextb = atomicAdd(&g_cam_counter, 1);  // prefetch next id
        nextb = __shfl_sync(0xffffffffu, nextb, 0);

        const int base = batch * S;

        u32 al2[P], ah2[P];     // f16x2 pre-scaled av halves (2 samples each)
        u64 a0[P], a1[P];       // f32x2 accumulators (residual init)

        #pragma unroll
        for (int p = 0; p < P; p++) {
            int b0 = base + 2 * p, b1 = b0 + 1;
            bool v0 = b0 < B, v1 = b1 < B;
            float x0 = v0 ? f1[b0 * 32 + l] : 0.0f;
            float x1 = v1 ? f1[b1 * 32 + l] : 0.0f;
            float y0 = v0 ? f2[b0 * 32 + l] : 0.0f;
            float y1 = v1 ? f2[b1 * 32 + l] : 0.0f;
            a0[p] = pack2(x0, x1);
            a1[p] = pack2(y0, y1);
            al2[p] = f2h2(x0 * RS, x1 * RS);
            ah2[p] = f2h2(y0 * RS, y1 * RS);
        }

        // Diagonal + (l, l+32) pair — no communication
        #pragma unroll
        for (int p = 0; p < P; p++) {
            u32 td = tanh2(hmul2(al2[p], al2[p]));
            a0[p] = ffma2(h2f2(td), wdd0, a0[p]);
            u32 te = tanh2(hmul2(ah2[p], ah2[p]));
            a1[p] = ffma2(h2f2(te), wdd1, a1[p]);
            u32 tm = tanh2(hmul2(al2[p], ah2[p]));
            u64 tmf = h2f2(tm);
            a0[p] = ffma2(tmf, wmm0, a0[p]);
            a1[p] = ffma2(tmf, wmm1, a1[p]);
        }

        // Rolled m-loop keeps body (~1KB SASS) in L0 I$.
        #pragma unroll 1
        for (int m = 1; m < 32; m++) {
            const bool lo = l < (l ^ m);
            const float4 w = wq[m - 1][l];
            const u64 wxx = pack2(w.x, w.x);
            const u64 wyy = pack2(w.y, w.y);
            const u64 wzz = pack2(w.z, w.z);
            const u64 www = pack2(w.w, w.w);
            #pragma unroll
            for (int p = 0; p < P; p++) {
                // same-half pairs: one f16x2 tanh serves both lanes of the pair
                u32 send2 = lo ? ah2[p] : al2[p];
                u32 x2 = __shfl_xor_sync(0xffffffffu, send2, m);
                u32 sc2 = lo ? al2[p] : ah2[p];
                u32 t2 = tanh2(hmul2(sc2, x2));
                u32 to2 = __shfl_xor_sync(0xffffffffu, t2, m);
                u32 tl2 = lo ? t2 : to2;   // T_lo[l][l^m]   (2 samples)
                u32 th2 = lo ? to2 : t2;   // T_hi[l][l^m]
                a0[p] = ffma2(h2f2(tl2), wxx, a0[p]);
                a1[p] = ffma2(h2f2(th2), wyy, a1[p]);
                // cross-half: T[l][(l^m)+32]; partner's value is T[l+32][l^m]
                u32 xh2 = __shfl_xor_sync(0xffffffffu, ah2[p], m);
                u32 ta2 = tanh2(hmul2(al2[p], xh2));
                u32 tb2 = __shfl_xor_sync(0xffffffffu, ta2, m);
                a0[p] = ffma2(h2f2(ta2), wzz, a0[p]);
                a1[p] = ffma2(h2f2(tb2), www, a1[p]);
            }
        }

        #pragma unroll
        for (int p = 0; p < P; p++) {
            float2 r0 = unpack2(a0[p]);
            float2 r1 = unpack2(a1[p]);
            int b0 = base + 2 * p, b1 = b0 + 1;
            if (b0 < B) {
                out[b0 * 64 + l]      = 0.1f * fmaxf(r0.x, 0.0f);
                out[b0 * 64 + 32 + l] = 0.1f * fmaxf(r1.x, 0.0f);
            }
            if (b1 < B) {
                out[b1 * 64 + l]      = 0.1f * fmaxf(r0.y, 0.0f);
                out[b1 * 64 + 32 + l] = 0.1f * fmaxf(r1.y, 0.0f);
            }
        }

        batch = nextb;
    }
}

extern "C" void kernel_launch(void* const* d_in, const int* in_sizes, int n_in,
                              void* d_out, int out_size) {
    const float* f1  = (const float*)d_in[0];
    const float* f2  = (const float*)d_in[1];
    const float* Wca = (const float*)d_in[2];
    const float* Wcv = (const float*)d_in[3];
    float* out = (float*)d_out;

    const int B = in_sizes[0] / 32;

    void* ctr = nullptr;
    cudaGetSymbolAddress(&ctr, g_cam_counter);
    cudaMemsetAsync(ctr, 0, sizeof(int));

    // 8 blocks/SM x 148 SMs x 4 warps = 4736 warps; atomic work stealing.
    cam_kernel<<<1184, 128>>>(f1, f2, Wca, Wcv, out, B);
}

// round 5
// speedup vs baseline: 1.2798x; 1.1463x over previous
#include <cuda_runtime.h>

// CAM_43344809951340: per-sample symmetric tanh outer-product attention.
// T[i][j] = tanh(av_i*av_j*s), symmetric 64x64; rows contracted with Wca/Wcv.
// Lane l owns rows l and l+32. XOR pairing computes each unique tanh once.
// f16x2 sample-pair packing: one tanh.approx.f16x2 = 2 tanhs, one SHFL = 2
// values. R5: accumulate in f16x2 (HFMA2) with f32x2 flush every 8 m-steps —
// kills the per-unit f16->f32 conversions that stalled R4 on the issue pipe.

#define RS 0.35355339059327379f   // sqrt(1/8)
#define S 8                       // samples per warp-iteration (4 f16x2 pairs)
#define P 4

typedef unsigned long long u64;
typedef unsigned int u32;

__device__ int g_cam_counter;

// ---- packed-op helpers ----
__device__ __forceinline__ u64 ffma2(u64 a, u64 b, u64 c) {
    u64 d; asm("fma.rn.f32x2 %0,%1,%2,%3;" : "=l"(d) : "l"(a), "l"(b), "l"(c));
    return d;
}
__device__ __forceinline__ u64 pack2(float lo, float hi) {
    u64 d; asm("mov.b64 %0,{%1,%2};" : "=l"(d) : "f"(lo), "f"(hi));
    return d;
}
__device__ __forceinline__ float2 unpack2(u64 a) {
    float2 r; asm("mov.b64 {%0,%1},%2;" : "=f"(r.x), "=f"(r.y) : "l"(a));
    return r;
}
__device__ __forceinline__ u32 hmul2(u32 a, u32 b) {
    u32 d; asm("mul.rn.f16x2 %0,%1,%2;" : "=r"(d) : "r"(a), "r"(b));
    return d;
}
__device__ __forceinline__ u32 hfma2(u32 a, u32 b, u32 c) {
    u32 d; asm("fma.rn.f16x2 %0,%1,%2,%3;" : "=r"(d) : "r"(a), "r"(b), "r"(c));
    return d;
}
__device__ __forceinline__ u32 tanh2(u32 a) {
    u32 d; asm("tanh.approx.f16x2 %0,%1;" : "=r"(d) : "r"(a));
    return d;
}
// pack two f32 into f16x2 (first source -> HIGH half, so pass (hi, lo))
__device__ __forceinline__ u32 f2h2(float lo, float hi) {
    u32 d; asm("cvt.rn.f16x2.f32 %0,%1,%2;" : "=r"(d) : "f"(hi), "f"(lo));
    return d;
}
// widen f16x2 -> f32x2 (low->low)
__device__ __forceinline__ u64 h2f2(u32 h) {
    u64 d;
    asm("{.reg .f16 h0,h1; .reg .f32 f0,f1;\n\t"
        "mov.b32 {h0,h1},%1;\n\t"
        "cvt.f32.f16 f0,h0; cvt.f32.f16 f1,h1;\n\t"
        "mov.b64 %0,{f0,f1};}" : "=l"(d) : "r"(h));
    return d;
}

__global__ __launch_bounds__(128, 8)
void cam_kernel(const float* __restrict__ f1, const float* __restrict__ f2,
                const float* __restrict__ Wca, const float* __restrict__ Wcv,
                float* __restrict__ out, int B)
{
    // Per-(m,lane) weight table, pre-packed as broadcast f16x2 (LDS.128/m):
    //  .x = {Wca[l^m]}x2        (lo-lo pair, row l)
    //  .y = {Wcv[(l^m)+32]}x2   (hi-hi pair, row l+32)
    //  .z = {Wca[(l^m)+32]}x2   (cross, row l)
    //  .w = {Wcv[l^m]}x2        (cross, row l+32)
    __shared__ uint4 wq[31][32];

    const int tid = threadIdx.x;
    for (int idx = tid; idx < 31 * 32; idx += blockDim.x) {
        int m = (idx >> 5) + 1;
        int l2 = idx & 31;
        int j = l2 ^ m;
        uint4 e;
        e.x = f2h2(Wca[j],      Wca[j]);
        e.y = f2h2(Wcv[j + 32], Wcv[j + 32]);
        e.z = f2h2(Wca[j + 32], Wca[j + 32]);
        e.w = f2h2(Wcv[j],      Wcv[j]);
        wq[m - 1][l2] = e;
    }
    __syncthreads();

    const int l = tid & 31;
    // per-lane constant weights (diag + (l,l+32) pair), f32x2 broadcast
    const u64 wdd0 = pack2(Wca[l], Wca[l]);
    const u64 wdd1 = pack2(Wcv[l + 32], Wcv[l + 32]);
    const u64 wmm0 = pack2(Wca[l + 32], Wca[l + 32]);
    const u64 wmm1 = pack2(Wcv[l], Wcv[l]);
    const u64 ONE2 = pack2(1.0f, 1.0f);

    const int nbatch = (B + S - 1) / S;

    int batch = 0;
    if (l == 0) batch = atomicAdd(&g_cam_counter, 1);
    batch = __shfl_sync(0xffffffffu, batch, 0);

    while (batch < nbatch) {
        int nextb = 0;
        if (l == 0) nextb = atomicAdd(&g_cam_counter, 1);  // prefetch next id
        nextb = __shfl_sync(0xffffffffu, nextb, 0);

        const int base = batch * S;

        u32 al2[P], ah2[P];     // f16x2 pre-scaled av halves (2 samples each)
        u64 a0[P], a1[P];       // f32x2 master accumulators
        u32 p0[P], p1[P];       // f16x2 partial accumulators

        #pragma unroll
        for (int p = 0; p < P; p++) {
            int b0 = base + 2 * p, b1 = b0 + 1;
            bool v0 = b0 < B, v1 = b1 < B;
            float x0 = v0 ? f1[b0 * 32 + l] : 0.0f;
            float x1 = v1 ? f1[b1 * 32 + l] : 0.0f;
            float y0 = v0 ? f2[b0 * 32 + l] : 0.0f;
            float y1 = v1 ? f2[b1 * 32 + l] : 0.0f;
            a0[p] = pack2(x0, x1);            // residual init
            a1[p] = pack2(y0, y1);
            al2[p] = f2h2(x0 * RS, x1 * RS);
            ah2[p] = f2h2(y0 * RS, y1 * RS);
            p0[p] = 0u; p1[p] = 0u;
        }

        // Diagonal + (l, l+32) pair — no communication, f32x2 path
        #pragma unroll
        for (int p = 0; p < P; p++) {
            a0[p] = ffma2(h2f2(tanh2(hmul2(al2[p], al2[p]))), wdd0, a0[p]);
            a1[p] = ffma2(h2f2(tanh2(hmul2(ah2[p], ah2[p]))), wdd1, a1[p]);
            u64 tmf = h2f2(tanh2(hmul2(al2[p], ah2[p])));
            a0[p] = ffma2(tmf, wmm0, a0[p]);
            a1[p] = ffma2(tmf, wmm1, a1[p]);
        }

        // Rolled m-loop keeps body in L0 I$.
        #pragma unroll 1
        for (int m = 1; m < 32; m++) {
            const bool lo = l < (l ^ m);
            const uint4 w = wq[m - 1][l];
            #pragma unroll
            for (int p = 0; p < P; p++) {
                // same-half pairs: one f16x2 tanh serves both lanes of a pair
                u32 send2 = lo ? ah2[p] : al2[p];
                u32 x2 = __shfl_xor_sync(0xffffffffu, send2, m);
                u32 sc2 = lo ? al2[p] : ah2[p];
                u32 t2 = tanh2(hmul2(sc2, x2));
                u32 to2 = __shfl_xor_sync(0xffffffffu, t2, m);
                u32 tl2 = lo ? t2 : to2;   // T_lo[l][l^m]
                u32 th2 = lo ? to2 : t2;   // T_hi[l][l^m]
                p0[p] = hfma2(tl2, w.x, p0[p]);
                p1[p] = hfma2(th2, w.y, p1[p]);
                // cross-half: T[l][(l^m)+32]; partner's value is T[l+32][l^m]
                u32 xh2 = __shfl_xor_sync(0xffffffffu, ah2[p], m);
                u32 ta2 = tanh2(hmul2(al2[p], xh2));
                u32 tb2 = __shfl_xor_sync(0xffffffffu, ta2, m);
                p0[p] = hfma2(ta2, w.z, p0[p]);
                p1[p] = hfma2(tb2, w.w, p1[p]);
            }
            if ((m & 7) == 0) {   // flush partials (<=16 f16 terms) to f32x2
                #pragma unroll
                for (int p = 0; p < P; p++) {
                    a0[p] = ffma2(h2f2(p0[p]), ONE2, a0[p]);
                    a1[p] = ffma2(h2f2(p1[p]), ONE2, a1[p]);
                    p0[p] = 0u; p1[p] = 0u;
                }
            }
        }
        #pragma unroll
        for (int p = 0; p < P; p++) {   // final flush (m=25..31)
            a0[p] = ffma2(h2f2(p0[p]), ONE2, a0[p]);
            a1[p] = ffma2(h2f2(p1[p]), ONE2, a1[p]);
        }

        #pragma unroll
        for (int p = 0; p < P; p++) {
            float2 r0 = unpack2(a0[p]);
            float2 r1 = unpack2(a1[p]);
            int b0 = base + 2 * p, b1 = b0 + 1;
            if (b0 < B) {
                out[b0 * 64 + l]      = 0.1f * fmaxf(r0.x, 0.0f);
                out[b0 * 64 + 32 + l] = 0.1f * fmaxf(r1.x, 0.0f);
            }
            if (b1 < B) {
                out[b1 * 64 + l]      = 0.1f * fmaxf(r0.y, 0.0f);
                out[b1 * 64 + 32 + l] = 0.1f * fmaxf(r1.y, 0.0f);
            }
        }

        batch = nextb;
    }
}

extern "C" void kernel_launch(void* const* d_in, const int* in_sizes, int n_in,
                              void* d_out, int out_size) {
    const float* f1  = (const float*)d_in[0];
    const float* f2  = (const float*)d_in[1];
    const float* Wca = (const float*)d_in[2];
    const float* Wcv = (const float*)d_in[3];
    float* out = (float*)d_out;

    const int B = in_sizes[0] / 32;

    void* ctr = nullptr;
    cudaGetSymbolAddress(&ctr, g_cam_counter);
    cudaMemsetAsync(ctr, 0, sizeof(int));

    // 8 blocks/SM x 148 SMs x 4 warps; atomic work stealing with prefetch.
    cam_kernel<<<1184, 128>>>(f1, f2, Wca, Wcv, out, B);
}